// round 1
// baseline (speedup 1.0000x reference)
#include <cuda_runtime.h>
#include <math.h>

// SwitchGate fused kernel: GEMM(X @ W^T + b) -> softmax(E=64) -> top2 mask ->
// batch-dim denominator -> * capacity(5).
//
// Shapes (hardcoded per reference): X[B=4][S=4096][D=4096] f32, W[E=64][D=4096] f32,
// b[E=64] f32, out[B][S][E] f32.
//
// Block layout: one block handles TS=16 consecutive s-values x all B=4 batches
// x all E=64 experts. GEMM tile: M=64 rows (row = si*4 + b), N=64, K streamed
// in KC=64 chunks through shared memory. The batch-sum denominator is fully
// block-local, so the whole op fuses into a single launch with no scratch.

#define B_DIM 4
#define S_DIM 4096
#define D_DIM 4096
#define E_DIM 64

#define TS 16            // s-values per block
#define MROWS 64         // TS * B_DIM
#define KC 64            // K chunk
#define LPAD 68          // padded smem row length (floats), multiple of 4

__global__ __launch_bounds__(256)
void switch_gate_kernel(const float* __restrict__ X,
                        const float* __restrict__ W,
                        const float* __restrict__ bias,
                        float* __restrict__ out)
{
    __shared__ float Xs[MROWS][LPAD];   // also reused for logits after GEMM
    __shared__ float Ws[E_DIM][LPAD];
    __shared__ float s_p1[MROWS], s_p2[MROWS];
    __shared__ int   s_i1[MROWS], s_i2[MROWS];

    const int s0  = blockIdx.x * TS;
    const int tid = threadIdx.x;
    const int ty  = tid >> 4;   // 0..15 (row group)
    const int tx  = tid & 15;   // 0..15 (col group)

    float acc[4][4];
    #pragma unroll
    for (int r = 0; r < 4; r++)
        #pragma unroll
        for (int c = 0; c < 4; c++) acc[r][c] = 0.0f;

    for (int k0 = 0; k0 < D_DIM; k0 += KC) {
        // ---- Stage X tile: 64 rows x 64 k (1024 float4, 4 per thread) ----
        #pragma unroll
        for (int i = 0; i < 4; i++) {
            int id  = tid + 256 * i;
            int row = id >> 4;      // 0..63
            int kq  = id & 15;      // 0..15
            int si  = row >> 2;
            int b   = row & 3;
            const float4 v = *reinterpret_cast<const float4*>(
                &X[((size_t)b * S_DIM + (s0 + si)) * D_DIM + k0 + kq * 4]);
            *reinterpret_cast<float4*>(&Xs[row][kq * 4]) = v;
        }
        // ---- Stage W tile: 64 experts x 64 k ----
        #pragma unroll
        for (int i = 0; i < 4; i++) {
            int id = tid + 256 * i;
            int e  = id >> 4;
            int kq = id & 15;
            const float4 v = *reinterpret_cast<const float4*>(
                &W[(size_t)e * D_DIM + k0 + kq * 4]);
            *reinterpret_cast<float4*>(&Ws[e][kq * 4]) = v;
        }
        __syncthreads();

        // ---- Compute: each thread does a 4x4 register tile ----
        #pragma unroll 8
        for (int k = 0; k < KC; k++) {
            float a[4], bb[4];
            #pragma unroll
            for (int j = 0; j < 4; j++) a[j]  = Xs[ty + 16 * j][k];
            #pragma unroll
            for (int j = 0; j < 4; j++) bb[j] = Ws[tx + 16 * j][k];
            #pragma unroll
            for (int r = 0; r < 4; r++)
                #pragma unroll
                for (int c = 0; c < 4; c++)
                    acc[r][c] = fmaf(a[r], bb[c], acc[r][c]);
        }
        __syncthreads();
    }

    // ---- Write logits (+bias) into smem (reuse Xs) ----
    #pragma unroll
    for (int r = 0; r < 4; r++)
        #pragma unroll
        for (int c = 0; c < 4; c++)
            Xs[ty + 16 * r][tx + 16 * c] = acc[r][c] + bias[tx + 16 * c];
    __syncthreads();

    // ---- Per-row softmax + top-2 (threads 0..63, one row each) ----
    // Ascending scan with strict '>' so ties keep the lower index,
    // matching jax.lax.top_k tie-breaking.
    if (tid < MROWS) {
        const int row = tid;
        float m = -INFINITY;
        #pragma unroll
        for (int e = 0; e < E_DIM; e++) m = fmaxf(m, Xs[row][e]);

        float sum = 0.0f;
        float v1 = -INFINITY, v2 = -INFINITY;
        int   i1 = 0, i2 = 0;
        #pragma unroll
        for (int e = 0; e < E_DIM; e++) {
            float l = Xs[row][e];
            sum += expf(l - m);
            if (l > v1)      { v2 = v1; i2 = i1; v1 = l; i1 = e; }
            else if (l > v2) { v2 = l;  i2 = e; }
        }
        float inv = 1.0f / sum;
        s_p1[row] = expf(v1 - m) * inv;
        s_p2[row] = expf(v2 - m) * inv;
        s_i1[row] = i1;
        s_i2[row] = i2;
    }
    __syncthreads();

    // ---- Epilogue: denominator over batch dim + scaled write ----
    // 16 si x 64 e = 1024 tasks, 4 per thread; consecutive tid -> consecutive e
    // for coalesced stores.
    #pragma unroll
    for (int i = 0; i < 4; i++) {
        int id = tid + 256 * i;
        int e  = id & 63;
        int si = id >> 6;

        float val[B_DIM];
        float den = 1e-6f;
        #pragma unroll
        for (int b = 0; b < B_DIM; b++) {
            int row = si * 4 + b;
            float v = 0.0f;
            if (e == s_i1[row]) v = s_p1[row];
            else if (e == s_i2[row]) v = s_p2[row];
            val[b] = v;
            den += v;
        }
        float scale = 5.0f / den;   // capacity = int(1.25 * B) = 5
        #pragma unroll
        for (int b = 0; b < B_DIM; b++) {
            out[((size_t)b * S_DIM + (s0 + si)) * E_DIM + e] = val[b] * scale;
        }
    }
}

extern "C" void kernel_launch(void* const* d_in, const int* in_sizes, int n_in,
                              void* d_out, int out_size)
{
    const float* X    = (const float*)d_in[0];
    const float* W    = (const float*)d_in[1];
    const float* bias = (const float*)d_in[2];
    float* out        = (float*)d_out;

    dim3 grid(S_DIM / TS);   // 256 blocks
    dim3 block(256);
    switch_gate_kernel<<<grid, block>>>(X, W, bias, out);
}

// round 2
// speedup vs baseline: 2.4555x; 2.4555x over previous
#include <cuda_runtime.h>
#include <cuda_bf16.h>
#include <math.h>
#include <stdint.h>

// SwitchGate fused, tensor-core edition.
// logits = X @ W^T + b via split-bf16 3-pass MMA (Ah*Bh + Ah*Bl + Al*Bh, fp32 accum)
// then softmax(E=64) -> top2 -> batch-dim denominator -> *capacity(5).
//
// X[4][4096][4096] f32, W[64][4096] f32, b[64] f32, out[4][4096][64] f32.
// Block: 16 s-values x 4 batches x 64 experts = 64x64 logits tile, K streamed
// in 64-wide chunks, register-double-buffered.

#define B_DIM 4
#define S_DIM 4096
#define D_DIM 4096
#define E_DIM 64

#define TS 16
#define MROWS 64
#define KC 64
#define NCHUNK (D_DIM / KC)   // 64
#define ASTR 72               // smem row stride in bf16 (144 B -> conflict-free ldmatrix)
#define LSTR 68               // logits smem stride (floats)

// Pre-split W (1 MB): hi = bf16(w), lo = bf16(w - hi)
__device__ __nv_bfloat16 g_Wh[E_DIM * D_DIM];
__device__ __nv_bfloat16 g_Wl[E_DIM * D_DIM];

__global__ void wsplit_kernel(const float* __restrict__ W) {
    int i = blockIdx.x * blockDim.x + threadIdx.x;
    if (i < E_DIM * D_DIM) {
        float x = W[i];
        __nv_bfloat16 h = __float2bfloat16(x);
        g_Wh[i] = h;
        g_Wl[i] = __float2bfloat16(x - __bfloat162float(h));
    }
}

__device__ __forceinline__ void ldm_x4(uint32_t& r0, uint32_t& r1, uint32_t& r2,
                                       uint32_t& r3, uint32_t addr) {
    asm volatile("ldmatrix.sync.aligned.m8n8.x4.shared.b16 {%0,%1,%2,%3}, [%4];\n"
                 : "=r"(r0), "=r"(r1), "=r"(r2), "=r"(r3)
                 : "r"(addr));
}

__device__ __forceinline__ void mma_bf16(float* c, const uint32_t* a,
                                         uint32_t b0, uint32_t b1) {
    asm volatile(
        "mma.sync.aligned.m16n8k16.row.col.f32.bf16.bf16.f32 "
        "{%0,%1,%2,%3}, {%4,%5,%6,%7}, {%8,%9}, {%0,%1,%2,%3};\n"
        : "+f"(c[0]), "+f"(c[1]), "+f"(c[2]), "+f"(c[3])
        : "r"(a[0]), "r"(a[1]), "r"(a[2]), "r"(a[3]), "r"(b0), "r"(b1));
}

__device__ __forceinline__ uint32_t pk(__nv_bfloat16 lo, __nv_bfloat16 hi) {
    return ((uint32_t)__bfloat16_as_ushort(hi) << 16) | (uint32_t)__bfloat16_as_ushort(lo);
}

__global__ __launch_bounds__(256, 2)
void switch_gate_mma(const float* __restrict__ X,
                     const float* __restrict__ bias,
                     float* __restrict__ out)
{
    // [Ah | Al | Bh | Bl], each 64 rows x ASTR bf16
    __shared__ __align__(16) unsigned char smem[4 * 64 * ASTR * 2];  // 36864 B
    __shared__ float sP1[MROWS], sP2[MROWS];
    __shared__ int   sI1[MROWS], sI2[MROWS];

    __nv_bfloat16* sAh = (__nv_bfloat16*)smem;
    __nv_bfloat16* sAl = sAh + MROWS * ASTR;
    __nv_bfloat16* sBh = sAl + MROWS * ASTR;
    __nv_bfloat16* sBl = sBh + E_DIM * ASTR;
    float* sLog = (float*)smem;  // [64][LSTR] overlays Ah+Al (17408 <= 18432 B)

    const int tid  = threadIdx.x;
    const int lane = tid & 31;
    const int wid  = tid >> 5;
    const int m0   = (wid >> 1) * 16;   // 4 m-groups
    const int n0   = (wid & 1) * 32;    // 2 n-groups
    const int s0   = blockIdx.x * TS;

    const uint32_t smem_u32 = (uint32_t)__cvta_generic_to_shared(smem);

    // ldmatrix.x4 A addresses: mats (m0,k0),(m0+8,k0),(m0,k0+8),(m0+8,k0+8)
    const int mat = lane >> 3;
    const uint32_t aAddr  = smem_u32 +
        (uint32_t)(((m0 + (mat & 1) * 8 + (lane & 7)) * ASTR + (mat >> 1) * 8) * 2);
    const uint32_t alAddr = aAddr + (uint32_t)(MROWS * ASTR * 2);

    // ldmatrix.x4 B addresses: mats (n,k0),(n,k0+8),(n+8,k0),(n+8,k0+8)
    const uint32_t bBase = smem_u32 + (uint32_t)(2 * MROWS * ASTR * 2);
    const int nb0 = n0 + ((lane >> 4) * 8) + (lane & 7);
    const uint32_t bkc = (uint32_t)((((lane >> 3) & 1) * 8) * 2);
    const uint32_t bAddr0 = bBase + (uint32_t)(nb0 * ASTR * 2) + bkc;
    const uint32_t bAddr1 = bBase + (uint32_t)((nb0 + 16) * ASTR * 2) + bkc;
    const uint32_t blOff  = (uint32_t)(E_DIM * ASTR * 2);

    // staging indices
    const int xrow0 = tid >> 4;   // +16*i
    const int xkq   = tid & 15;
    const int wrow0 = tid >> 3;   // +32*i
    const int wkc   = tid & 7;

    float4 xv[4];
    uint4  whv[2], wlv[2];

    float c[4][4];
    #pragma unroll
    for (int t = 0; t < 4; t++)
        #pragma unroll
        for (int u = 0; u < 4; u++) c[t][u] = 0.0f;

    auto loadRegs = [&](int k0) {
        #pragma unroll
        for (int i = 0; i < 4; i++) {
            int row = xrow0 + 16 * i;
            int b = row & 3, si = row >> 2;
            xv[i] = *reinterpret_cast<const float4*>(
                &X[((size_t)b * S_DIM + (s0 + si)) * (size_t)D_DIM + k0 + xkq * 4]);
        }
        #pragma unroll
        for (int i = 0; i < 2; i++) {
            int row = wrow0 + 32 * i;
            size_t off = (size_t)row * D_DIM + k0 + wkc * 8;
            whv[i] = *reinterpret_cast<const uint4*>(&g_Wh[off]);
            wlv[i] = *reinterpret_cast<const uint4*>(&g_Wl[off]);
        }
    };

    auto stage = [&]() {
        #pragma unroll
        for (int i = 0; i < 4; i++) {
            int row = xrow0 + 16 * i;
            float f0 = xv[i].x, f1 = xv[i].y, f2 = xv[i].z, f3 = xv[i].w;
            __nv_bfloat16 h0 = __float2bfloat16(f0), h1 = __float2bfloat16(f1);
            __nv_bfloat16 h2 = __float2bfloat16(f2), h3 = __float2bfloat16(f3);
            __nv_bfloat16 l0 = __float2bfloat16(f0 - __bfloat162float(h0));
            __nv_bfloat16 l1 = __float2bfloat16(f1 - __bfloat162float(h1));
            __nv_bfloat16 l2 = __float2bfloat16(f2 - __bfloat162float(h2));
            __nv_bfloat16 l3 = __float2bfloat16(f3 - __bfloat162float(h3));
            int off = row * ASTR + xkq * 4;
            *reinterpret_cast<uint2*>(&sAh[off]) = make_uint2(pk(h0, h1), pk(h2, h3));
            *reinterpret_cast<uint2*>(&sAl[off]) = make_uint2(pk(l0, l1), pk(l2, l3));
        }
        #pragma unroll
        for (int i = 0; i < 2; i++) {
            int row = wrow0 + 32 * i;
            int off = row * ASTR + wkc * 8;
            *reinterpret_cast<uint2*>(&sBh[off])     = make_uint2(whv[i].x, whv[i].y);
            *reinterpret_cast<uint2*>(&sBh[off + 4]) = make_uint2(whv[i].z, whv[i].w);
            *reinterpret_cast<uint2*>(&sBl[off])     = make_uint2(wlv[i].x, wlv[i].y);
            *reinterpret_cast<uint2*>(&sBl[off + 4]) = make_uint2(wlv[i].z, wlv[i].w);
        }
    };

    // prologue: stage chunk 0
    loadRegs(0);
    stage();
    __syncthreads();

    for (int ch = 0; ch < NCHUNK; ch++) {
        const bool more = (ch + 1 < NCHUNK);
        if (more) loadRegs((ch + 1) * KC);  // LDG in flight behind MMAs

        #pragma unroll
        for (int ks = 0; ks < 4; ks++) {
            const uint32_t koff = (uint32_t)(ks * 32);  // 16 bf16 = 32 B per k-step
            uint32_t ah[4], al[4];
            ldm_x4(ah[0], ah[1], ah[2], ah[3], aAddr + koff);
            ldm_x4(al[0], al[1], al[2], al[3], alAddr + koff);

            uint32_t bh[4][2], bl[4][2];
            {
                uint32_t q0, q1, q2, q3;
                ldm_x4(q0, q1, q2, q3, bAddr0 + koff);
                bh[0][0] = q0; bh[0][1] = q1; bh[1][0] = q2; bh[1][1] = q3;
                ldm_x4(q0, q1, q2, q3, bAddr1 + koff);
                bh[2][0] = q0; bh[2][1] = q1; bh[3][0] = q2; bh[3][1] = q3;
                ldm_x4(q0, q1, q2, q3, bAddr0 + blOff + koff);
                bl[0][0] = q0; bl[0][1] = q1; bl[1][0] = q2; bl[1][1] = q3;
                ldm_x4(q0, q1, q2, q3, bAddr1 + blOff + koff);
                bl[2][0] = q0; bl[2][1] = q1; bl[3][0] = q2; bl[3][1] = q3;
            }

            #pragma unroll
            for (int nt = 0; nt < 4; nt++) {
                mma_bf16(c[nt], ah, bh[nt][0], bh[nt][1]);  // hi*hi
                mma_bf16(c[nt], ah, bl[nt][0], bl[nt][1]);  // hi*lo
                mma_bf16(c[nt], al, bh[nt][0], bh[nt][1]);  // lo*hi
            }
        }

        __syncthreads();
        if (more) {
            stage();
            __syncthreads();
        }
    }

    // ---- write logits (+bias) to smem (overlays A tiles; safe after last sync) ----
    {
        int r1 = m0 + (lane >> 2);
        int cbase = n0 + (lane & 3) * 2;
        #pragma unroll
        for (int nt = 0; nt < 4; nt++) {
            int col = cbase + nt * 8;
            float b0 = bias[col], b1 = bias[col + 1];
            sLog[r1 * LSTR + col]           = c[nt][0] + b0;
            sLog[r1 * LSTR + col + 1]       = c[nt][1] + b1;
            sLog[(r1 + 8) * LSTR + col]     = c[nt][2] + b0;
            sLog[(r1 + 8) * LSTR + col + 1] = c[nt][3] + b1;
        }
    }
    __syncthreads();

    // ---- per-row softmax + top-2 (strict '>' keeps lower index on ties) ----
    if (tid < MROWS) {
        const int row = tid;
        float m = -INFINITY;
        #pragma unroll
        for (int e = 0; e < E_DIM; e++) m = fmaxf(m, sLog[row * LSTR + e]);
        float sum = 0.0f, v1 = -INFINITY, v2 = -INFINITY;
        int i1 = 0, i2 = 0;
        #pragma unroll
        for (int e = 0; e < E_DIM; e++) {
            float l = sLog[row * LSTR + e];
            sum += expf(l - m);
            if (l > v1)      { v2 = v1; i2 = i1; v1 = l; i1 = e; }
            else if (l > v2) { v2 = l;  i2 = e; }
        }
        float inv = 1.0f / sum;
        sP1[row] = expf(v1 - m) * inv;
        sP2[row] = expf(v2 - m) * inv;
        sI1[row] = i1;
        sI2[row] = i2;
    }
    __syncthreads();

    // ---- batch denominator + scaled coalesced write ----
    #pragma unroll
    for (int i = 0; i < 4; i++) {
        int id = tid + 256 * i;
        int e  = id & 63;
        int si = id >> 6;
        float val[B_DIM];
        float den = 1e-6f;
        #pragma unroll
        for (int b = 0; b < B_DIM; b++) {
            int row = si * 4 + b;
            float v = 0.0f;
            if (e == sI1[row]) v = sP1[row];
            else if (e == sI2[row]) v = sP2[row];
            val[b] = v;
            den += v;
        }
        float scale = 5.0f / den;  // capacity = int(1.25 * 4) = 5
        #pragma unroll
        for (int b = 0; b < B_DIM; b++)
            out[((size_t)b * S_DIM + (s0 + si)) * E_DIM + e] = val[b] * scale;
    }
}

extern "C" void kernel_launch(void* const* d_in, const int* in_sizes, int n_in,
                              void* d_out, int out_size)
{
    const float* X    = (const float*)d_in[0];
    const float* W    = (const float*)d_in[1];
    const float* bias = (const float*)d_in[2];
    float* out        = (float*)d_out;

    wsplit_kernel<<<(E_DIM * D_DIM + 255) / 256, 256>>>(W);
    switch_gate_mma<<<S_DIM / TS, 256>>>(X, bias, out);
}